// round 12
// baseline (speedup 1.0000x reference)
#include <cuda_runtime.h>
#include <cuda_bf16.h>
#include <math.h>
#include <stdint.h>

#define BB 16
#define LL 16384
#define CC 256
#define NH 8
#define HD 32
#define TILE 64
#define NTILES (LL / TILE)          // 256
#define NT_ALL (BB * NTILES)        // 4096
#define GRIDK2 148
#define SCALE_ATT 0.17677669529663687f
#define LN_EPS 1e-5f

#define PITCHXB 528u   // bytes per 256-col bf16 row (A, B, XBF, WQT)
#define PITCHT 144u    // bytes per 64-col bf16 row (+pad) (XT, PT)

// ---------------- device scratch ----------------
__device__ float g_wq[BB * CC * NH];
__device__ float g_qb[BB * NH];
__device__ float g_sg[BB * NH];
__device__ float g_bw[BB * NH];
__device__ __nv_bfloat16 g_part[BB * NTILES * NH * CC];  // bf16, L2-resident (32MB)
__device__ float g_md[BB * NTILES * NH * 4];
__device__ float g_attn[BB * CC];
__device__ __nv_bfloat16 g_bflat[CC * CC];        // W_ip^T bf16 [n][k]
__device__ float g_x[BB * CC];
__device__ float g_hn[BB * CC];
__device__ float g_h1[BB * 512];

// ---------------- helpers ----------------
__device__ __forceinline__ uint32_t smem_u32(const void* p) {
    uint32_t a;
    asm("{ .reg .u64 t; cvta.to.shared.u64 t, %1; cvt.u32.u64 %0, t; }" : "=r"(a) : "l"(p));
    return a;
}
__device__ __forceinline__ void ldsm_x4(uint32_t* r, uint32_t a) {
    asm volatile("ldmatrix.sync.aligned.m8n8.x4.shared.b16 {%0,%1,%2,%3}, [%4];"
                 : "=r"(r[0]), "=r"(r[1]), "=r"(r[2]), "=r"(r[3]) : "r"(a));
}
__device__ __forceinline__ void ldsm_x2(uint32_t* r, uint32_t a) {
    asm volatile("ldmatrix.sync.aligned.m8n8.x2.shared.b16 {%0,%1}, [%2];"
                 : "=r"(r[0]), "=r"(r[1]) : "r"(a));
}
__device__ __forceinline__ void mma16816(float* c, const uint32_t* a, const uint32_t* b) {
    asm volatile("mma.sync.aligned.m16n8k16.row.col.f32.bf16.bf16.f32 "
                 "{%0,%1,%2,%3}, {%4,%5,%6,%7}, {%8,%9}, {%0,%1,%2,%3};"
                 : "+f"(c[0]), "+f"(c[1]), "+f"(c[2]), "+f"(c[3])
                 : "r"(a[0]), "r"(a[1]), "r"(a[2]), "r"(a[3]), "r"(b[0]), "r"(b[1]));
}
// packed convert: low half = lo, high half = hi (PTX: first source -> high)
__device__ __forceinline__ uint32_t cvt2(float lo, float hi) {
    uint32_t r;
    asm("cvt.rn.bf16x2.f32 %0, %1, %2;" : "=r"(r) : "f"(hi), "f"(lo));
    return r;
}
__device__ __forceinline__ void cp_async16(uint32_t dst, const void* src) {
    asm volatile("cp.async.cg.shared.global [%0], [%1], 16;" :: "r"(dst), "l"(src));
}
__device__ __forceinline__ void cp_commit() {
    asm volatile("cp.async.commit_group;" ::: "memory");
}
__device__ __forceinline__ void cp_wait0() {
    asm volatile("cp.async.wait_group 0;" ::: "memory");
}

// ---------------- K0: W_ip^T -> bf16 [n][k] ----------------
__global__ void k0_wprep(const float* __restrict__ W_ip) {
    int k = blockIdx.x;
    int n = threadIdx.x;
    g_bflat[(size_t)n * CC + k] = __float2bfloat16(W_ip[(size_t)k * CC + n]);
}

// ---------------- K1: q-path prep ----------------
__global__ void k1_qprep(const float* __restrict__ query,
                         const float* __restrict__ g_q, const float* __restrict__ be_q,
                         const float* __restrict__ W_q, const float* __restrict__ b_q,
                         const float* __restrict__ W_kv, const float* __restrict__ b_kv,
                         const float* __restrict__ g_ip, const float* __restrict__ be_ip) {
    int b = blockIdx.x;
    int tid = threadIdx.x;
    __shared__ float qn[CC], qp[CC], wraw[CC * NH], rs[8], rs2[8];

    float v = query[b * CC + tid];
    float s = v, s2 = v * v;
    #pragma unroll
    for (int o = 16; o > 0; o >>= 1) {
        s  += __shfl_xor_sync(~0u, s,  o);
        s2 += __shfl_xor_sync(~0u, s2, o);
    }
    if ((tid & 31) == 0) { rs[tid >> 5] = s; rs2[tid >> 5] = s2; }
    __syncthreads();
    float tot = 0.f, tot2 = 0.f;
    #pragma unroll
    for (int i = 0; i < 8; i++) { tot += rs[i]; tot2 += rs2[i]; }
    float mean = tot * (1.0f / CC);
    float var  = tot2 * (1.0f / CC) - mean * mean;
    float rstd = rsqrtf(var + LN_EPS);
    qn[tid] = (v - mean) * rstd * g_q[tid] + be_q[tid];
    __syncthreads();

    float acc = b_q[tid];
    #pragma unroll 4
    for (int k = 0; k < CC; k++) acc += qn[k] * W_q[k * CC + tid];
    qp[tid] = acc;
    __syncthreads();

    int k = tid;
    float gk = g_ip[k];
    #pragma unroll
    for (int h = 0; h < NH; h++) {
        float a = 0.f;
        const float* wrow = W_kv + (size_t)k * (2 * CC) + h * HD;
        const float* qh = qp + h * HD;
        #pragma unroll
        for (int d = 0; d < HD; d++) a += qh[d] * wrow[d];
        wraw[k * NH + h] = a;
        g_wq[(b * CC + k) * NH + h] = gk * a;
    }
    if (tid < NH) {
        float a = 0.f;
        const float* qh = qp + tid * HD;
        const float* bk = b_kv + tid * HD;
        #pragma unroll
        for (int d = 0; d < HD; d++) a += qh[d] * bk[d];
        g_qb[b * NH + tid] = a;
    }
    __syncthreads();
    if (tid < NH) {
        float sg = 0.f, bw = 0.f;
        for (int kk = 0; kk < CC; kk++) {
            float r = wraw[kk * NH + tid];
            sg += g_ip[kk] * r;
            bw += be_ip[kk] * r;
        }
        g_sg[b * NH + tid] = sg;
        g_bw[b * NH + tid] = bw;
    }
}

// ---------------- K2 smem layout (bytes): persistent-B, occ=1 ----------------
#define SM_B     0u          // 256*528 = 135168 (persistent)
#define SM_A     135168u     // 64*528 = 33792 (A during GEMM; XBF after)
#define SM_XBF   135168u
#define SM_XT    168960u     // 256*144 = 36864 -> 205824
#define SM_REDS  205824u     // 2048
#define SM_SS    207872u     // 2048
#define SM_MRS   209920u     // 512
#define SM_MH    210432u     // 64
#define SM_PT    210496u     // 16*144 = 2304 -> 212800
#define SM_BIAS  212800u     // 1024
#define SM_WQT   213824u     // 8*528 = 4224 -> 218048
#define SM_TOTAL 218048u

extern __shared__ char k2smem[];

__global__ __launch_bounds__(256, 1)
void k2_main(const float* __restrict__ mem, const float* __restrict__ ior,
             const float* __restrict__ b_ip) {
    int tid = threadIdx.x;
    int wid = tid >> 5, lane = tid & 31;
    char* sb = k2smem;
    uint32_t sbase = smem_u32(sb);
    float* bias = (float*)(sb + SM_BIAS);
    float* s_s  = (float*)(sb + SM_SS);
    float* mrs  = (float*)(sb + SM_MRS);
    float* mh   = (float*)(sb + SM_MH);
    float* reds = (float*)(sb + SM_REDS);

    // ---- persistent B load (once): g_bflat [n][k] re-pitched 512B -> 528B ----
    #pragma unroll
    for (int i = 0; i < 32; i++) {
        int u = tid + i * 256;                // 8192 = 256 rows * 32 units
        int row = u >> 5, c16 = u & 31;
        cp_async16(sbase + SM_B + (uint32_t)row * PITCHXB + (uint32_t)c16 * 16,
                   (const char*)g_bflat + (size_t)row * 512 + c16 * 16);
    }
    cp_commit();
    bias[tid] = b_ip[tid];
    cp_wait0();
    __syncthreads();

    int wm = wid >> 2, wn = wid & 3;
    int m_base = wm * 32, n_base = wn * 64;
    int grp = lane >> 3, jj = lane & 7;
    int b_prev = -1;

    for (int t = blockIdx.x; t < NT_ALL; t += GRIDK2) {
        int b = t >> 8;            // NTILES = 256
        int tile = t & 255;

        __syncthreads();   // prior epilogue reads done; safe to overwrite A/WQT

        if (b != b_prev) {
            const float* wp = &g_wq[(size_t)(b * CC + tid) * NH];
            #pragma unroll
            for (int h = 0; h < NH; h++)
                *(__nv_bfloat16*)(sb + SM_WQT + (uint32_t)h * PITCHXB + (uint32_t)tid * 2)
                    = __float2bfloat16(wp[h]);
            b_prev = b;
        }

        // ---- A: fp32 -> bf16, full K=256 ----
        const float* memp = mem + ((size_t)b * LL + (size_t)tile * TILE) * CC;
        #pragma unroll
        for (int i = 0; i < 16; i++) {
            int f4 = tid + i * 256;               // 4096 = 64 rows * 64 f4
            int row = f4 >> 6, c4 = f4 & 63;
            float4 v = ((const float4*)(memp + (size_t)row * CC))[c4];
            uint2 u;
            u.x = cvt2(v.x, v.y); u.y = cvt2(v.z, v.w);
            *(uint2*)(sb + SM_A + (uint32_t)row * PITCHXB + (uint32_t)c4 * 8) = u;
        }
        __syncthreads();

        // ---- GEMM: x = A(64x256) @ B^T, single-pass bf16, full K ----
        float acc[2][8][4];
        #pragma unroll
        for (int mt = 0; mt < 2; mt++)
            #pragma unroll
            for (int nt = 0; nt < 8; nt++)
                #pragma unroll
                for (int e = 0; e < 4; e++) acc[mt][nt][e] = 0.f;

        #pragma unroll
        for (int k8 = 0; k8 < 16; k8++) {
            int k0 = k8 * 16;
            uint32_t arow = (uint32_t)(m_base + (grp & 1) * 8 + jj) * PITCHXB
                          + (uint32_t)(k0 + (grp >> 1) * 8) * 2;
            uint32_t a[2][4];
            #pragma unroll
            for (int mt = 0; mt < 2; mt++)
                ldsm_x4(a[mt], sbase + SM_A + arow + (uint32_t)mt * 16 * PITCHXB);
            uint32_t brow = (uint32_t)(n_base + (grp >> 1) * 8 + jj) * PITCHXB
                          + (uint32_t)(k0 + (grp & 1) * 8) * 2;
            #pragma unroll
            for (int np = 0; np < 4; np++) {
                uint32_t bb[4];
                ldsm_x4(bb, sbase + SM_B + brow + (uint32_t)np * 16 * PITCHXB);
                #pragma unroll
                for (int mt = 0; mt < 2; mt++) {
                    mma16816(acc[mt][np * 2 + 0], a[mt], bb + 0);
                    mma16816(acc[mt][np * 2 + 1], a[mt], bb + 2);
                }
            }
        }
        __syncthreads();    // A dead; XBF/XT overlays live

        // ---- E1: bias+relu -> XBF [j][c] + XT [c][j], LN partials ----
        #pragma unroll
        for (int mt = 0; mt < 2; mt++) {
            int r0 = m_base + mt * 16 + (lane >> 2);
            float s0 = 0.f, q0 = 0.f, s1 = 0.f, q1 = 0.f;
            #pragma unroll
            for (int nt = 0; nt < 8; nt++) {
                int n = n_base + nt * 8 + (lane & 3) * 2;
                float b0 = bias[n], b1 = bias[n + 1];
                float x00 = fmaxf(acc[mt][nt][0] + b0, 0.f);
                float x01 = fmaxf(acc[mt][nt][1] + b1, 0.f);
                float x10 = fmaxf(acc[mt][nt][2] + b0, 0.f);
                float x11 = fmaxf(acc[mt][nt][3] + b1, 0.f);
                s0 += x00 + x01; q0 += x00 * x00 + x01 * x01;
                s1 += x10 + x11; q1 += x10 * x10 + x11 * x11;
                *(uint32_t*)(sb + SM_XBF + (uint32_t)r0 * PITCHXB + (uint32_t)n * 2)
                    = cvt2(x00, x01);
                *(uint32_t*)(sb + SM_XBF + (uint32_t)(r0 + 8) * PITCHXB + (uint32_t)n * 2)
                    = cvt2(x10, x11);
                *(__nv_bfloat16*)(sb + SM_XT + (uint32_t)n * PITCHT + (uint32_t)r0 * 2)
                    = __float2bfloat16(x00);
                *(__nv_bfloat16*)(sb + SM_XT + (uint32_t)(n + 1) * PITCHT + (uint32_t)r0 * 2)
                    = __float2bfloat16(x01);
                *(__nv_bfloat16*)(sb + SM_XT + (uint32_t)n * PITCHT + (uint32_t)(r0 + 8) * 2)
                    = __float2bfloat16(x10);
                *(__nv_bfloat16*)(sb + SM_XT + (uint32_t)(n + 1) * PITCHT + (uint32_t)(r0 + 8) * 2)
                    = __float2bfloat16(x11);
            }
            #pragma unroll
            for (int o = 1; o <= 2; o <<= 1) {
                s0 += __shfl_xor_sync(~0u, s0, o); q0 += __shfl_xor_sync(~0u, q0, o);
                s1 += __shfl_xor_sync(~0u, s1, o); q1 += __shfl_xor_sync(~0u, q1, o);
            }
            if ((lane & 3) == 0) {
                reds[(wn * 64 + r0) * 2]         = s0;
                reds[(wn * 64 + r0) * 2 + 1]     = q0;
                reds[(wn * 64 + r0 + 8) * 2]     = s1;
                reds[(wn * 64 + r0 + 8) * 2 + 1] = q1;
            }
        }
        __syncthreads();

        // ---- E2: finalize LN stats (64 rows) ----
        if (tid < 64) {
            float s = reds[tid * 2] + reds[(64 + tid) * 2]
                    + reds[(128 + tid) * 2] + reds[(192 + tid) * 2];
            float q = reds[tid * 2 + 1] + reds[(64 + tid) * 2 + 1]
                    + reds[(128 + tid) * 2 + 1] + reds[(192 + tid) * 2 + 1];
            float mean = s * (1.0f / CC);
            float var  = q * (1.0f / CC) - mean * mean;
            mrs[tid] = mean;
            mrs[64 + tid] = rsqrtf(var + LN_EPS);
        }
        __syncthreads();

        // ---- E3: score dots via MMA (warps 0-3) ----
        if (wid < 4) {
            float cd[4] = {0.f, 0.f, 0.f, 0.f};
            #pragma unroll
            for (int k8 = 0; k8 < 16; k8++) {
                uint32_t a[4];
                ldsm_x4(a, sbase + SM_XBF
                           + (uint32_t)(wid * 16 + (grp & 1) * 8 + jj) * PITCHXB
                           + (uint32_t)(k8 * 16 + (grp >> 1) * 8) * 2);
                uint32_t bb[2];
                ldsm_x2(bb, sbase + SM_WQT + (uint32_t)(lane & 7) * PITCHXB
                           + (uint32_t)(k8 * 16 + ((lane >> 3) & 1) * 8) * 2);
                mma16816(cd, a, bb);
            }
            int r = wid * 16 + (lane >> 2);
            int h0 = (lane & 3) * 2;
            int glb = tile * TILE;
            #pragma unroll
            for (int e = 0; e < 4; e++) {
                int row = r + (e >> 1) * 8;
                int h = h0 + (e & 1);
                float mean = mrs[row], rstd = mrs[64 + row];
                float sv = (rstd * (cd[e] - mean * g_sg[b * NH + h])
                            + g_bw[b * NH + h] + g_qb[b * NH + h]) * SCALE_ATT
                           * ior[((size_t)b * NH + h) * LL + glb + row];
                s_s[row * 8 + h] = sv;
            }
        }
        __syncthreads();

        // ---- E4: per-head max ----
        {
            int h = wid;
            float m = fmaxf(s_s[lane * 8 + h], s_s[(lane + 32) * 8 + h]);
            #pragma unroll
            for (int o = 16; o > 0; o >>= 1) m = fmaxf(m, __shfl_xor_sync(~0u, m, o));
            if (lane == 0) mh[h] = m;
        }
        __syncthreads();
        #pragma unroll
        for (int i = 0; i < 2; i++) {
            int idx = tid + i * 256;
            s_s[idx] = __expf(s_s[idx] - mh[idx & 7]);
        }
        __syncthreads();
        {
            int h = wid;
            float D = 0.f, Q = 0.f;
            #pragma unroll
            for (int i = 0; i < 2; i++) {
                int j = lane + i * 32;
                float p = s_s[j * 8 + h];
                D += p;
                Q += p * mrs[64 + j] * mrs[j];
            }
            #pragma unroll
            for (int o = 16; o > 0; o >>= 1) {
                D += __shfl_xor_sync(~0u, D, o);
                Q += __shfl_xor_sync(~0u, Q, o);
            }
            if (lane == 0) {
                float* md = &g_md[(size_t)((b * NTILES + tile) * NH + h) * 4];
                md[0] = mh[h];
                md[1] = D;
                md[2] = Q;
            }
        }
        if (tid < 64) {
            float rstd = mrs[64 + tid];
            #pragma unroll
            for (int h = 0; h < NH; h++)
                *(__nv_bfloat16*)(sb + SM_PT + (uint32_t)h * PITCHT + (uint32_t)tid * 2)
                    = __float2bfloat16(s_s[tid * 8 + h] * rstd);
        }
        for (int i = tid; i < 576; i += 256)       // zero pad rows 8..15
            *(unsigned short*)(sb + SM_PT + 8 * PITCHT + (uint32_t)i * 2) = 0;
        __syncthreads();

        // ---- E6: T = pT @ x via MMA; B = XT [c][j] non-trans x4 ----
        {
            float ct[4][4];
            #pragma unroll
            for (int q = 0; q < 4; q++)
                #pragma unroll
                for (int e = 0; e < 4; e++) ct[q][e] = 0.f;
            #pragma unroll
            for (int k8 = 0; k8 < 4; k8++) {
                int j0 = k8 * 16;
                uint32_t a[4];
                ldsm_x4(a, sbase + SM_PT + (uint32_t)((grp & 1) * 8 + jj) * PITCHT
                           + (uint32_t)(j0 + (grp >> 1) * 8) * 2);
                #pragma unroll
                for (int np = 0; np < 2; np++) {
                    uint32_t bb[4];
                    ldsm_x4(bb, sbase + SM_XT
                               + (uint32_t)(wid * 32 + np * 16 + (grp >> 1) * 8 + jj) * PITCHT
                               + (uint32_t)(j0 + (grp & 1) * 8) * 2);
                    mma16816(ct[np * 2 + 0], a, bb + 0);
                    mma16816(ct[np * 2 + 1], a, bb + 2);
                }
            }
            int h = lane >> 2;
            __nv_bfloat16* gp = g_part + (size_t)((b * NTILES + tile) * NH + h) * CC;
            #pragma unroll
            for (int q = 0; q < 4; q++) {
                int c = wid * 32 + (q >> 1) * 16 + (q & 1) * 8 + (lane & 3) * 2;
                *(uint32_t*)&gp[c] = cvt2(ct[q][0], ct[q][1]);
            }
        }
    }
}

// ---------------- K3: combine tiles + project through W_v ----------------
__global__ void k3_combine(const float* __restrict__ W_kv, const float* __restrict__ b_kv,
                           const float* __restrict__ g_ip, const float* __restrict__ be_ip) {
    int b = blockIdx.x >> 3, h = blockIdx.x & 7, tid = threadIdx.x;
    __shared__ float w_s[NTILES];
    __shared__ float tv[CC];
    __shared__ float redx[256];
    __shared__ float rsc[8], rsc2[8], rsc3[8];

    const float* md = &g_md[(size_t)((b * NTILES + tid) * NH + h) * 4];
    float Mt = md[0], Dt = md[1], Qt = md[2];

    float m = Mt;
    #pragma unroll
    for (int o = 16; o > 0; o >>= 1) m = fmaxf(m, __shfl_xor_sync(~0u, m, o));
    if ((tid & 31) == 0) rsc[tid >> 5] = m;
    __syncthreads();
    float M = rsc[0];
    #pragma unroll
    for (int i = 1; i < 8; i++) M = fmaxf(M, rsc[i]);

    float sc = __expf(Mt - M);
    w_s[tid] = sc;
    float dp = sc * Dt, qp = sc * Qt;
    __syncthreads();
    #pragma unroll
    for (int o = 16; o > 0; o >>= 1) {
        dp += __shfl_xor_sync(~0u, dp, o);
        qp += __shfl_xor_sync(~0u, qp, o);
    }
    if ((tid & 31) == 0) { rsc2[tid >> 5] = dp; rsc3[tid >> 5] = qp; }
    __syncthreads();
    float D = 0.f, Q = 0.f;
    #pragma unroll
    for (int i = 0; i < 8; i++) { D += rsc2[i]; Q += rsc3[i]; }

    // high-MLP combine: 2 accumulators + unroll 8
    float acc0 = 0.f, acc1 = 0.f;
    const __nv_bfloat16* base = g_part + (size_t)(b * NTILES) * NH * CC
                              + (size_t)h * CC + tid;
    const size_t stride = (size_t)NH * CC;
    #pragma unroll 8
    for (int t2 = 0; t2 < NTILES; t2 += 2) {
        acc0 += w_s[t2]     * __bfloat162float(base[(size_t)t2 * stride]);
        acc1 += w_s[t2 + 1] * __bfloat162float(base[(size_t)(t2 + 1) * stride]);
    }
    tv[tid] = g_ip[tid] * ((acc0 + acc1) - Q) / D + be_ip[tid];
    __syncthreads();

    int d = tid & 31, g = tid >> 5;
    float a = 0.f;
    #pragma unroll 8
    for (int k = g * 32; k < g * 32 + 32; k++)
        a += tv[k] * W_kv[(size_t)k * (2 * CC) + CC + h * HD + d];
    redx[g * 32 + d] = a;
    __syncthreads();
    if (tid < 32) {
        float s = 0.f;
        #pragma unroll
        for (int gg = 0; gg < 8; gg++) s += redx[gg * 32 + tid];
        g_attn[b * CC + h * HD + tid] = s + b_kv[CC + h * HD + tid];
    }
}

// ---------------- K4a/b/c ----------------
__global__ void k4a_ln(const float* __restrict__ query,
                       const float* __restrict__ g_f, const float* __restrict__ be_f) {
    int b = blockIdx.x, tid = threadIdx.x;
    __shared__ float rs[8], rs2[8];
    float x = g_attn[b * CC + tid] + query[b * CC + tid];
    g_x[b * CC + tid] = x;
    float s = x, s2 = x * x;
    #pragma unroll
    for (int o = 16; o > 0; o >>= 1) {
        s  += __shfl_xor_sync(~0u, s,  o);
        s2 += __shfl_xor_sync(~0u, s2, o);
    }
    if ((tid & 31) == 0) { rs[tid >> 5] = s; rs2[tid >> 5] = s2; }
    __syncthreads();
    float tot = 0.f, tot2 = 0.f;
    #pragma unroll
    for (int i = 0; i < 8; i++) { tot += rs[i]; tot2 += rs2[i]; }
    float mean = tot * (1.0f / CC);
    float var  = tot2 * (1.0f / CC) - mean * mean;
    float rstd = rsqrtf(var + LN_EPS);
    g_hn[b * CC + tid] = (x - mean) * rstd * g_f[tid] + be_f[tid];
}

__global__ void k4b_ffn1(const float* __restrict__ W1, const float* __restrict__ b1) {
    int b = blockIdx.y, tid = threadIdx.x;
    int f = blockIdx.x * 64 + (tid & 63);
    int ks = tid >> 6;
    __shared__ float red[256];
    const float* hn = &g_hn[b * CC];
    float acc = 0.f;
    #pragma unroll 8
    for (int k = ks * 64; k < ks * 64 + 64; k++)
        acc += hn[k] * W1[(size_t)k * 512 + f];
    red[tid] = acc;
    __syncthreads();
    if (tid < 64) {
        float a = red[tid] + red[64 + tid] + red[128 + tid] + red[192 + tid] + b1[f];
        g_h1[b * 512 + f] = 0.5f * a * (1.0f + erff(a * 0.70710678118654752f));
    }
}

__global__ void k4c_ffn2(const float* __restrict__ W2, const float* __restrict__ b2,
                         float* __restrict__ out) {
    int b = blockIdx.y, tid = threadIdx.x;
    int c = blockIdx.x * 64 + (tid & 63);
    int ks = tid >> 6;
    __shared__ float red[256];
    const float* h1 = &g_h1[b * 512];
    float acc = 0.f;
    #pragma unroll 8
    for (int k = ks * 128; k < ks * 128 + 128; k++)
        acc += h1[k] * W2[(size_t)k * CC + c];
    red[tid] = acc;
    __syncthreads();
    if (tid < 64) {
        float a = red[tid] + red[64 + tid] + red[128 + tid] + red[192 + tid];
        out[b * CC + c] = g_x[b * CC + c] + a + b2[c];
    }
}

// ---------------- launch ----------------
extern "C" void kernel_launch(void* const* d_in, const int* in_sizes, int n_in,
                              void* d_out, int out_size) {
    const float* query = (const float*)d_in[0];
    const float* mem   = (const float*)d_in[1];
    const float* ior   = (const float*)d_in[2];
    const float* W_ip  = (const float*)d_in[3];
    const float* b_ip  = (const float*)d_in[4];
    const float* g_ipp = (const float*)d_in[5];
    const float* be_ip = (const float*)d_in[6];
    const float* W_q   = (const float*)d_in[7];
    const float* b_q   = (const float*)d_in[8];
    const float* W_kv  = (const float*)d_in[9];
    const float* b_kv  = (const float*)d_in[10];
    const float* g_q   = (const float*)d_in[11];
    const float* be_q  = (const float*)d_in[12];
    const float* g_f   = (const float*)d_in[13];
    const float* be_f  = (const float*)d_in[14];
    const float* W1    = (const float*)d_in[15];
    const float* b1    = (const float*)d_in[16];
    const float* W2    = (const float*)d_in[17];
    const float* b2    = (const float*)d_in[18];
    float* out = (float*)d_out;

    cudaFuncSetAttribute(k2_main, cudaFuncAttributeMaxDynamicSharedMemorySize,
                         (int)SM_TOTAL);

    k0_wprep<<<256, 256>>>(W_ip);
    k1_qprep<<<BB, 256>>>(query, g_q, be_q, W_q, b_q, W_kv, b_kv, g_ipp, be_ip);
    k2_main<<<GRIDK2, 256, SM_TOTAL>>>(mem, ior, b_ip);
    k3_combine<<<BB * NH, 256>>>(W_kv, b_kv, g_ipp, be_ip);
    k4a_ln<<<BB, 256>>>(query, g_f, be_f);
    k4b_ffn1<<<dim3(8, BB), 256>>>(W1, b1);
    k4c_ffn2<<<dim3(4, BB), 256>>>(W2, b2, out);
}

// round 13
// speedup vs baseline: 1.1795x; 1.1795x over previous
#include <cuda_runtime.h>
#include <cuda_bf16.h>
#include <math.h>
#include <stdint.h>

#define BB 16
#define LL 16384
#define CC 256
#define NH 8
#define HD 32
#define TILE 64
#define NTILES (LL / TILE)          // 256
#define SCALE_ATT 0.17677669529663687f
#define LN_EPS 1e-5f

#define PITCHH 272u    // bytes per 128-col bf16 row (A/B half tiles)
#define PITCHXB 528u   // bytes per 256-col bf16 row (XBF, WQT)
#define PITCHT 144u    // bytes per 64-col bf16 row (+pad) (XT, PT)

// ---------------- device scratch ----------------
__device__ float g_wq[BB * CC * NH];
__device__ float g_qb[BB * NH];
__device__ float g_sg[BB * NH];
__device__ float g_bw[BB * NH];
__device__ __nv_bfloat16 g_part[BB * NTILES * NH * CC];  // bf16 (17MB, L2-resident)
__device__ float g_md[BB * NTILES * NH * 4];
__device__ float g_attn[BB * CC];
__device__ __nv_bfloat16 g_bflat[CC * CC];        // W_ip^T bf16 [n][k]
__device__ float g_x[BB * CC];
__device__ float g_hn[BB * CC];
__device__ float g_h1[BB * 512];

// ---------------- helpers ----------------
__device__ __forceinline__ uint32_t smem_u32(const void* p) {
    uint32_t a;
    asm("{ .reg .u64 t; cvta.to.shared.u64 t, %1; cvt.u32.u64 %0, t; }" : "=r"(a) : "l"(p));
    return a;
}
__device__ __forceinline__ void ldsm_x4(uint32_t* r, uint32_t a) {
    asm volatile("ldmatrix.sync.aligned.m8n8.x4.shared.b16 {%0,%1,%2,%3}, [%4];"
                 : "=r"(r[0]), "=r"(r[1]), "=r"(r[2]), "=r"(r[3]) : "r"(a));
}
__device__ __forceinline__ void ldsm_x2(uint32_t* r, uint32_t a) {
    asm volatile("ldmatrix.sync.aligned.m8n8.x2.shared.b16 {%0,%1}, [%2];"
                 : "=r"(r[0]), "=r"(r[1]) : "r"(a));
}
__device__ __forceinline__ void mma16816(float* c, const uint32_t* a, const uint32_t* b) {
    asm volatile("mma.sync.aligned.m16n8k16.row.col.f32.bf16.bf16.f32 "
                 "{%0,%1,%2,%3}, {%4,%5,%6,%7}, {%8,%9}, {%0,%1,%2,%3};"
                 : "+f"(c[0]), "+f"(c[1]), "+f"(c[2]), "+f"(c[3])
                 : "r"(a[0]), "r"(a[1]), "r"(a[2]), "r"(a[3]), "r"(b[0]), "r"(b[1]));
}
// packed convert: low half = lo, high half = hi (PTX: first source -> high)
__device__ __forceinline__ uint32_t cvt2(float lo, float hi) {
    uint32_t r;
    asm("cvt.rn.bf16x2.f32 %0, %1, %2;" : "=r"(r) : "f"(hi), "f"(lo));
    return r;
}
__device__ __forceinline__ void cp_async16(uint32_t dst, const void* src) {
    asm volatile("cp.async.cg.shared.global [%0], [%1], 16;" :: "r"(dst), "l"(src));
}
__device__ __forceinline__ void cp_commit() {
    asm volatile("cp.async.commit_group;" ::: "memory");
}
__device__ __forceinline__ void cp_wait0() {
    asm volatile("cp.async.wait_group 0;" ::: "memory");
}

// ---------------- K0: W_ip^T -> bf16 [n][k] ----------------
__global__ void k0_wprep(const float* __restrict__ W_ip) {
    int k = blockIdx.x;
    int n = threadIdx.x;
    g_bflat[(size_t)n * CC + k] = __float2bfloat16(W_ip[(size_t)k * CC + n]);
}

// ---------------- K1: q-path prep ----------------
__global__ void k1_qprep(const float* __restrict__ query,
                         const float* __restrict__ g_q, const float* __restrict__ be_q,
                         const float* __restrict__ W_q, const float* __restrict__ b_q,
                         const float* __restrict__ W_kv, const float* __restrict__ b_kv,
                         const float* __restrict__ g_ip, const float* __restrict__ be_ip) {
    int b = blockIdx.x;
    int tid = threadIdx.x;
    __shared__ float qn[CC], qp[CC], wraw[CC * NH], rs[8], rs2[8];

    float v = query[b * CC + tid];
    float s = v, s2 = v * v;
    #pragma unroll
    for (int o = 16; o > 0; o >>= 1) {
        s  += __shfl_xor_sync(~0u, s,  o);
        s2 += __shfl_xor_sync(~0u, s2, o);
    }
    if ((tid & 31) == 0) { rs[tid >> 5] = s; rs2[tid >> 5] = s2; }
    __syncthreads();
    float tot = 0.f, tot2 = 0.f;
    #pragma unroll
    for (int i = 0; i < 8; i++) { tot += rs[i]; tot2 += rs2[i]; }
    float mean = tot * (1.0f / CC);
    float var  = tot2 * (1.0f / CC) - mean * mean;
    float rstd = rsqrtf(var + LN_EPS);
    qn[tid] = (v - mean) * rstd * g_q[tid] + be_q[tid];
    __syncthreads();

    float acc = b_q[tid];
    #pragma unroll 4
    for (int k = 0; k < CC; k++) acc += qn[k] * W_q[k * CC + tid];
    qp[tid] = acc;
    __syncthreads();

    int k = tid;
    float gk = g_ip[k];
    #pragma unroll
    for (int h = 0; h < NH; h++) {
        float a = 0.f;
        const float* wrow = W_kv + (size_t)k * (2 * CC) + h * HD;
        const float* qh = qp + h * HD;
        #pragma unroll
        for (int d = 0; d < HD; d++) a += qh[d] * wrow[d];
        wraw[k * NH + h] = a;
        g_wq[(b * CC + k) * NH + h] = gk * a;
    }
    if (tid < NH) {
        float a = 0.f;
        const float* qh = qp + tid * HD;
        const float* bk = b_kv + tid * HD;
        #pragma unroll
        for (int d = 0; d < HD; d++) a += qh[d] * bk[d];
        g_qb[b * NH + tid] = a;
    }
    __syncthreads();
    if (tid < NH) {
        float sg = 0.f, bw = 0.f;
        for (int kk = 0; kk < CC; kk++) {
            float r = wraw[kk * NH + tid];
            sg += g_ip[kk] * r;
            bw += be_ip[kk] * r;
        }
        g_sg[b * NH + tid] = sg;
        g_bw[b * NH + tid] = bw;
    }
}

// ---------------- K2 smem layout (bytes), TILE=64, K-half staging, occ=2 ----------------
#define SM_A     0u          // 64*272 = 17408
#define SM_B     17408u      // 256*272 = 69632 -> 87040
#define SM_BIAS  87040u      // 1024
#define SM_WQT   88064u      // 8*528 = 4224 -> 92288
#define SM_TOTAL 92288u
// overlays (valid after GEMM; A+B dead, all < 87040):
#define SM_XBF   0u          // 64*528 = 33792
#define SM_XT    33792u      // 256*144 = 36864 -> 70656
#define SM_REDS  70656u      // 2048
#define SM_SS    72704u      // 2048
#define SM_MRS   74752u      // 512
#define SM_MH    75264u      // 64
#define SM_PT    75328u      // 16*144 = 2304 -> 77632

extern __shared__ char k2smem[];

__global__ __launch_bounds__(256, 2)
void k2_main(const float* __restrict__ mem, const float* __restrict__ ior,
             const float* __restrict__ b_ip) {
    int b = blockIdx.y, tile = blockIdx.x, tid = threadIdx.x;
    int wid = tid >> 5, lane = tid & 31;
    char* sb = k2smem;
    uint32_t sbase = smem_u32(sb);
    float* bias = (float*)(sb + SM_BIAS);
    float* s_s  = (float*)(sb + SM_SS);
    float* mrs  = (float*)(sb + SM_MRS);
    float* mh   = (float*)(sb + SM_MH);
    float* reds = (float*)(sb + SM_REDS);

    // constants: bias + wq^T [h][k] bf16
    bias[tid] = b_ip[tid];
    {
        const float* wp = &g_wq[(size_t)(b * CC + tid) * NH];
        #pragma unroll
        for (int h = 0; h < NH; h++)
            *(__nv_bfloat16*)(sb + SM_WQT + (uint32_t)h * PITCHXB + (uint32_t)tid * 2)
                = __float2bfloat16(wp[h]);
    }

    int wm = wid >> 2, wn = wid & 3;
    int m_base = wm * 32, n_base = wn * 64;
    int grp = lane >> 3, jj = lane & 7;

    float acc[2][8][4];
    #pragma unroll
    for (int mt = 0; mt < 2; mt++)
        #pragma unroll
        for (int nt = 0; nt < 8; nt++)
            #pragma unroll
            for (int e = 0; e < 4; e++) acc[mt][nt][e] = 0.f;

    const float* memp = mem + ((size_t)b * LL + (size_t)tile * TILE) * CC;

    for (int h = 0; h < 2; h++) {
        __syncthreads();
        // B half via cp.async: g_bflat [n][k], half-k slice, re-pitch 256B->272B
        #pragma unroll
        for (int i = 0; i < 16; i++) {
            int u = tid + i * 256;                // 4096 = 256 rows * 16 units
            int row = u >> 4, c16 = u & 15;
            cp_async16(sbase + SM_B + (uint32_t)row * PITCHH + (uint32_t)c16 * 16,
                       (const char*)g_bflat + (size_t)row * 512 + h * 256 + c16 * 16);
        }
        cp_commit();
        // A half: fp32 -> bf16
        #pragma unroll
        for (int i = 0; i < 8; i++) {
            int f4 = tid + i * 256;               // 2048 = 64 rows * 32 f4
            int row = f4 >> 5, c4 = f4 & 31;
            float4 v = ((const float4*)(memp + (size_t)row * CC + h * 128))[c4];
            uint2 u;
            u.x = cvt2(v.x, v.y); u.y = cvt2(v.z, v.w);
            *(uint2*)(sb + SM_A + (uint32_t)row * PITCHH + (uint32_t)c4 * 8) = u;
        }
        cp_wait0();
        __syncthreads();

        // single-pass bf16 MMA over this K-half
        #pragma unroll
        for (int k8 = 0; k8 < 8; k8++) {
            int k0 = k8 * 16;
            uint32_t arow = (uint32_t)(m_base + (grp & 1) * 8 + jj) * PITCHH
                          + (uint32_t)(k0 + (grp >> 1) * 8) * 2;
            uint32_t a[2][4];
            #pragma unroll
            for (int mt = 0; mt < 2; mt++)
                ldsm_x4(a[mt], sbase + SM_A + arow + (uint32_t)mt * 16 * PITCHH);
            uint32_t brow = (uint32_t)(n_base + (grp >> 1) * 8 + jj) * PITCHH
                          + (uint32_t)(k0 + (grp & 1) * 8) * 2;
            #pragma unroll
            for (int np = 0; np < 4; np++) {
                uint32_t bb[4];
                ldsm_x4(bb, sbase + SM_B + brow + (uint32_t)np * 16 * PITCHH);
                #pragma unroll
                for (int mt = 0; mt < 2; mt++) {
                    mma16816(acc[mt][np * 2 + 0], a[mt], bb + 0);
                    mma16816(acc[mt][np * 2 + 1], a[mt], bb + 2);
                }
            }
        }
    }
    __syncthreads();    // tiles dead; overlays live

    // E1: bias+relu -> XBF [j][c] + XT [c][j], LN partials
    #pragma unroll
    for (int mt = 0; mt < 2; mt++) {
        int r0 = m_base + mt * 16 + (lane >> 2);
        float s0 = 0.f, q0 = 0.f, s1 = 0.f, q1 = 0.f;
        #pragma unroll
        for (int nt = 0; nt < 8; nt++) {
            int n = n_base + nt * 8 + (lane & 3) * 2;
            float b0 = bias[n], b1 = bias[n + 1];
            float x00 = fmaxf(acc[mt][nt][0] + b0, 0.f);
            float x01 = fmaxf(acc[mt][nt][1] + b1, 0.f);
            float x10 = fmaxf(acc[mt][nt][2] + b0, 0.f);
            float x11 = fmaxf(acc[mt][nt][3] + b1, 0.f);
            s0 += x00 + x01; q0 += x00 * x00 + x01 * x01;
            s1 += x10 + x11; q1 += x10 * x10 + x11 * x11;
            *(uint32_t*)(sb + SM_XBF + (uint32_t)r0 * PITCHXB + (uint32_t)n * 2)
                = cvt2(x00, x01);
            *(uint32_t*)(sb + SM_XBF + (uint32_t)(r0 + 8) * PITCHXB + (uint32_t)n * 2)
                = cvt2(x10, x11);
            *(__nv_bfloat16*)(sb + SM_XT + (uint32_t)n * PITCHT + (uint32_t)r0 * 2)
                = __float2bfloat16(x00);
            *(__nv_bfloat16*)(sb + SM_XT + (uint32_t)(n + 1) * PITCHT + (uint32_t)r0 * 2)
                = __float2bfloat16(x01);
            *(__nv_bfloat16*)(sb + SM_XT + (uint32_t)n * PITCHT + (uint32_t)(r0 + 8) * 2)
                = __float2bfloat16(x10);
            *(__nv_bfloat16*)(sb + SM_XT + (uint32_t)(n + 1) * PITCHT + (uint32_t)(r0 + 8) * 2)
                = __float2bfloat16(x11);
        }
        #pragma unroll
        for (int o = 1; o <= 2; o <<= 1) {
            s0 += __shfl_xor_sync(~0u, s0, o); q0 += __shfl_xor_sync(~0u, q0, o);
            s1 += __shfl_xor_sync(~0u, s1, o); q1 += __shfl_xor_sync(~0u, q1, o);
        }
        if ((lane & 3) == 0) {
            reds[(wn * 64 + r0) * 2]         = s0;
            reds[(wn * 64 + r0) * 2 + 1]     = q0;
            reds[(wn * 64 + r0 + 8) * 2]     = s1;
            reds[(wn * 64 + r0 + 8) * 2 + 1] = q1;
        }
    }
    __syncthreads();

    // E2: finalize LN stats (64 rows)
    if (tid < 64) {
        float s = reds[tid * 2] + reds[(64 + tid) * 2]
                + reds[(128 + tid) * 2] + reds[(192 + tid) * 2];
        float q = reds[tid * 2 + 1] + reds[(64 + tid) * 2 + 1]
                + reds[(128 + tid) * 2 + 1] + reds[(192 + tid) * 2 + 1];
        float mean = s * (1.0f / CC);
        float var  = q * (1.0f / CC) - mean * mean;
        mrs[tid] = mean;
        mrs[64 + tid] = rsqrtf(var + LN_EPS);
    }
    __syncthreads();

    // E3: score dots via MMA (warps 0-3: 16 rows each, full K=256)
    if (wid < 4) {
        float cd[4] = {0.f, 0.f, 0.f, 0.f};
        #pragma unroll
        for (int k8 = 0; k8 < 16; k8++) {
            uint32_t a[4];
            ldsm_x4(a, sbase + SM_XBF
                       + (uint32_t)(wid * 16 + (grp & 1) * 8 + jj) * PITCHXB
                       + (uint32_t)(k8 * 16 + (grp >> 1) * 8) * 2);
            uint32_t bb[2];
            ldsm_x2(bb, sbase + SM_WQT + (uint32_t)(lane & 7) * PITCHXB
                       + (uint32_t)(k8 * 16 + ((lane >> 3) & 1) * 8) * 2);
            mma16816(cd, a, bb);
        }
        int r = wid * 16 + (lane >> 2);
        int h0 = (lane & 3) * 2;
        int glb = tile * TILE;
        #pragma unroll
        for (int e = 0; e < 4; e++) {
            int row = r + (e >> 1) * 8;
            int h = h0 + (e & 1);
            float mean = mrs[row], rstd = mrs[64 + row];
            float sv = (rstd * (cd[e] - mean * g_sg[b * NH + h])
                        + g_bw[b * NH + h] + g_qb[b * NH + h]) * SCALE_ATT
                       * ior[((size_t)b * NH + h) * LL + glb + row];
            s_s[row * 8 + h] = sv;
        }
    }
    __syncthreads();

    // E4: per-head max (warp wid owns head wid, 64 j)
    {
        int h = wid;
        float m = fmaxf(s_s[lane * 8 + h], s_s[(lane + 32) * 8 + h]);
        #pragma unroll
        for (int o = 16; o > 0; o >>= 1) m = fmaxf(m, __shfl_xor_sync(~0u, m, o));
        if (lane == 0) mh[h] = m;
    }
    __syncthreads();
    // exp (512 values, 2 per thread)
    #pragma unroll
    for (int i = 0; i < 2; i++) {
        int idx = tid + i * 256;
        s_s[idx] = __expf(s_s[idx] - mh[idx & 7]);
    }
    __syncthreads();
    // D, Q per head + pT bf16 [h][j] (rstd folded)
    {
        int h = wid;
        float D = 0.f, Q = 0.f;
        #pragma unroll
        for (int i = 0; i < 2; i++) {
            int j = lane + i * 32;
            float p = s_s[j * 8 + h];
            D += p;
            Q += p * mrs[64 + j] * mrs[j];
        }
        #pragma unroll
        for (int o = 16; o > 0; o >>= 1) {
            D += __shfl_xor_sync(~0u, D, o);
            Q += __shfl_xor_sync(~0u, Q, o);
        }
        if (lane == 0) {
            float* md = &g_md[(size_t)((b * NTILES + tile) * NH + h) * 4];
            md[0] = mh[h];
            md[1] = D;
            md[2] = Q;
        }
    }
    if (tid < 64) {
        float rstd = mrs[64 + tid];
        #pragma unroll
        for (int h = 0; h < NH; h++)
            *(__nv_bfloat16*)(sb + SM_PT + (uint32_t)h * PITCHT + (uint32_t)tid * 2)
                = __float2bfloat16(s_s[tid * 8 + h] * rstd);
    }
    for (int i = tid; i < 576; i += 256)       // zero pad rows 8..15
        *(unsigned short*)(sb + SM_PT + 8 * PITCHT + (uint32_t)i * 2) = 0;
    __syncthreads();

    // E6: T = pT @ x via MMA; B = XT [c][j] non-trans x4; warp owns 32 c-cols
    {
        float ct[4][4];
        #pragma unroll
        for (int q = 0; q < 4; q++)
            #pragma unroll
            for (int e = 0; e < 4; e++) ct[q][e] = 0.f;
        #pragma unroll
        for (int k8 = 0; k8 < 4; k8++) {
            int j0 = k8 * 16;
            uint32_t a[4];
            ldsm_x4(a, sbase + SM_PT + (uint32_t)((grp & 1) * 8 + jj) * PITCHT
                       + (uint32_t)(j0 + (grp >> 1) * 8) * 2);
            #pragma unroll
            for (int np = 0; np < 2; np++) {
                uint32_t bb[4];
                ldsm_x4(bb, sbase + SM_XT
                           + (uint32_t)(wid * 32 + np * 16 + (grp >> 1) * 8 + jj) * PITCHT
                           + (uint32_t)(j0 + (grp & 1) * 8) * 2);
                mma16816(ct[np * 2 + 0], a, bb + 0);
                mma16816(ct[np * 2 + 1], a, bb + 2);
            }
        }
        int h = lane >> 2;
        __nv_bfloat16* gp = g_part + (size_t)((b * NTILES + tile) * NH + h) * CC;
        #pragma unroll
        for (int q = 0; q < 4; q++) {
            int c = wid * 32 + (q >> 1) * 16 + (q & 1) * 8 + (lane & 3) * 2;
            *(uint32_t*)&gp[c] = cvt2(ct[q][0], ct[q][1]);
        }
    }
}

// ---------------- K3: combine tiles + project through W_v ----------------
// 256 threads: M/D/Q reductions use tid = tile index (256 tiles);
// combine phase: thread handles tile-half (tid>>7) x channel-pair 2*(tid&127)
// with bf16x2 loads -> 128 iterations of 4B loads, halves merged via smem.
__global__ void k3_combine(const float* __restrict__ W_kv, const float* __restrict__ b_kv,
                           const float* __restrict__ g_ip, const float* __restrict__ be_ip) {
    int b = blockIdx.x >> 3, h = blockIdx.x & 7, tid = threadIdx.x;
    __shared__ float w_s[NTILES];
    __shared__ float pacc[2][CC];
    __shared__ float tv[CC];
    __shared__ float redx[256];
    __shared__ float rsc[8], rsc2[8], rsc3[8];

    const float* md = &g_md[(size_t)((b * NTILES + tid) * NH + h) * 4];
    float Mt = md[0], Dt = md[1], Qt = md[2];

    float m = Mt;
    #pragma unroll
    for (int o = 16; o > 0; o >>= 1) m = fmaxf(m, __shfl_xor_sync(~0u, m, o));
    if ((tid & 31) == 0) rsc[tid >> 5] = m;
    __syncthreads();
    float M = rsc[0];
    #pragma unroll
    for (int i = 1; i < 8; i++) M = fmaxf(M, rsc[i]);

    float sc = __expf(Mt - M);
    w_s[tid] = sc;
    float dp = sc * Dt, qp = sc * Qt;
    __syncthreads();
    #pragma unroll
    for (int o = 16; o > 0; o >>= 1) {
        dp += __shfl_xor_sync(~0u, dp, o);
        qp += __shfl_xor_sync(~0u, qp, o);
    }
    if ((tid & 31) == 0) { rsc2[tid >> 5] = dp; rsc3[tid >> 5] = qp; }
    __syncthreads();
    float D = 0.f, Q = 0.f;
    #pragma unroll
    for (int i = 0; i < 8; i++) { D += rsc2[i]; Q += rsc3[i]; }

    // combine: half of tiles x channel pair, bf16x2 loads
    {
        int half = tid >> 7, c2 = tid & 127;
        const __nv_bfloat16* basep = g_part
            + (size_t)(b * NTILES + half * 128) * NH * CC
            + (size_t)h * CC + (size_t)c2 * 2;
        const size_t stride = (size_t)NH * CC;
        const float* wh = &w_s[half * 128];
        float a0 = 0.f, a1 = 0.f;
        #pragma unroll 8
        for (int t2 = 0; t2 < 128; t2++) {
            __nv_bfloat162 v = *(const __nv_bfloat162*)(basep + (size_t)t2 * stride);
            float w = wh[t2];
            a0 += w * __bfloat162float(v.x);
            a1 += w * __bfloat162float(v.y);
        }
        pacc[half][c2 * 2]     = a0;
        pacc[half][c2 * 2 + 1] = a1;
    }
    __syncthreads();
    tv[tid] = g_ip[tid] * ((pacc[0][tid] + pacc[1][tid]) - Q) / D + be_ip[tid];
    __syncthreads();

    int d = tid & 31, g = tid >> 5;
    float a = 0.f;
    #pragma unroll 8
    for (int k = g * 32; k < g * 32 + 32; k++)
        a += tv[k] * W_kv[(size_t)k * (2 * CC) + CC + h * HD + d];
    redx[g * 32 + d] = a;
    __syncthreads();
    if (tid < 32) {
        float s = 0.f;
        #pragma unroll
        for (int gg = 0; gg < 8; gg++) s += redx[gg * 32 + tid];
        g_attn[b * CC + h * HD + tid] = s + b_kv[CC + h * HD + tid];
    }
}

// ---------------- K4a/b/c ----------------
__global__ void k4a_ln(const float* __restrict__ query,
                       const float* __restrict__ g_f, const float* __restrict__ be_f) {
    int b = blockIdx.x, tid = threadIdx.x;
    __shared__ float rs[8], rs2[8];
    float x = g_attn[b * CC + tid] + query[b * CC + tid];
    g_x[b * CC + tid] = x;
    float s = x, s2 = x * x;
    #pragma unroll
    for (int o = 16; o > 0; o >>= 1) {
        s  += __shfl_xor_sync(~0u, s,  o);
        s2 += __shfl_xor_sync(~0u, s2, o);
    }
    if ((tid & 31) == 0) { rs[tid >> 5] = s; rs2[tid >> 5] = s2; }
    __syncthreads();
    float tot = 0.f, tot2 = 0.f;
    #pragma unroll
    for (int i = 0; i < 8; i++) { tot += rs[i]; tot2 += rs2[i]; }
    float mean = tot * (1.0f / CC);
    float var  = tot2 * (1.0f / CC) - mean * mean;
    float rstd = rsqrtf(var + LN_EPS);
    g_hn[b * CC + tid] = (x - mean) * rstd * g_f[tid] + be_f[tid];
}

__global__ void k4b_ffn1(const float* __restrict__ W1, const float* __restrict__ b1) {
    int b = blockIdx.y, tid = threadIdx.x;
    int f = blockIdx.x * 64 + (tid & 63);
    int ks = tid >> 6;
    __shared__ float red[256];
    const float* hn = &g_hn[b * CC];
    float acc = 0.f;
    #pragma unroll 8
    for (int k = ks * 64; k < ks * 64 + 64; k++)
        acc += hn[k] * W1[(size_t)k * 512 + f];
    red[tid] = acc;
    __syncthreads();
    if (tid < 64) {
        float a = red[tid] + red[64 + tid] + red[128 + tid] + red[192 + tid] + b1[f];
        g_h1[b * 512 + f] = 0.5f * a * (1.0f + erff(a * 0.70710678118654752f));
    }
}

__global__ void k4c_ffn2(const float* __restrict__ W2, const float* __restrict__ b2,
                         float* __restrict__ out) {
    int b = blockIdx.y, tid = threadIdx.x;
    int c = blockIdx.x * 64 + (tid & 63);
    int ks = tid >> 6;
    __shared__ float red[256];
    const float* h1 = &g_h1[b * 512];
    float acc = 0.f;
    #pragma unroll 8
    for (int k = ks * 128; k < ks * 128 + 128; k++)
        acc += h1[k] * W2[(size_t)k * CC + c];
    red[tid] = acc;
    __syncthreads();
    if (tid < 64) {
        float a = red[tid] + red[64 + tid] + red[128 + tid] + red[192 + tid];
        out[b * CC + c] = g_x[b * CC + c] + a + b2[c];
    }
}

// ---------------- launch ----------------
extern "C" void kernel_launch(void* const* d_in, const int* in_sizes, int n_in,
                              void* d_out, int out_size) {
    const float* query = (const float*)d_in[0];
    const float* mem   = (const float*)d_in[1];
    const float* ior   = (const float*)d_in[2];
    const float* W_ip  = (const float*)d_in[3];
    const float* b_ip  = (const float*)d_in[4];
    const float* g_ipp = (const float*)d_in[5];
    const float* be_ip = (const float*)d_in[6];
    const float* W_q   = (const float*)d_in[7];
    const float* b_q   = (const float*)d_in[8];
    const float* W_kv  = (const float*)d_in[9];
    const float* b_kv  = (const float*)d_in[10];
    const float* g_q   = (const float*)d_in[11];
    const float* be_q  = (const float*)d_in[12];
    const float* g_f   = (const float*)d_in[13];
    const float* be_f  = (const float*)d_in[14];
    const float* W1    = (const float*)d_in[15];
    const float* b1    = (const float*)d_in[16];
    const float* W2    = (const float*)d_in[17];
    const float* b2    = (const float*)d_in[18];
    float* out = (float*)d_out;

    cudaFuncSetAttribute(k2_main, cudaFuncAttributeMaxDynamicSharedMemorySize,
                         (int)SM_TOTAL);

    k0_wprep<<<256, 256>>>(W_ip);
    k1_qprep<<<BB, 256>>>(query, g_q, be_q, W_q, b_q, W_kv, b_kv, g_ipp, be_ip);
    k2_main<<<dim3(NTILES, BB), 256, SM_TOTAL>>>(mem, ior, b_ip);
    k3_combine<<<BB * NH, 256>>>(W_kv, b_kv, g_ipp, be_ip);
    k4a_ln<<<BB, 256>>>(query, g_f, be_f);
    k4b_ffn1<<<dim3(8, BB), 256>>>(W1, b1);
    k4c_ffn2<<<dim3(4, BB), 256>>>(W2, b2, out);
}